// round 14
// baseline (speedup 1.0000x reference)
#include <cuda_runtime.h>
#include <cstdint>

#define T_STEPS 128
#define BATCH   256
#define D1      2048
#define D2      2048
#define M_TOTAL (T_STEPS * BATCH)      // 32768 GEMM rows

#define BM 128          // CTA tile M
#define BN 64           // CTA tile N
#define BK 128          // K chunk (int8 elems)
#define NSTAGE 4
#define NCHUNK (D1 / BK)               // 16
#define NPLANE 4                       // total digit planes
#define PPL    2                       // planes per pair

#define B_PLANE   (BN * 128)                    // 8192 per digit plane
#define MASK_OFF  (PPL * B_PLANE)               // 16384
#define STAGE_BYTES (MASK_OFF + BM * 16)        // 18432 (B planes + x-bit tile)
#define SMEM_BYTES  (NSTAGE * STAGE_BYTES)      // 73728 -> 2 CTAs/SM

// x bitmask, packed in mma-fragment byte order (validated R9, rel_err = 0):
//   word w of a row covers k in [32w, 32w+32); bit (8q+b)   = x[32w + 4q + b]      (k-low)
//                                              bit (8q+4+b) = x[32w + 16 + 4q + b] (k-high)
__device__ uint32_t g_xmask[(size_t)M_TOTAL * (D1 / 32)];   // 8MB
__device__ int8_t   g_w8[(size_t)NPLANE * D2 * D1];         // digit planes c0..c3 (W*2^33)
__device__ float    g_curp[2][(size_t)M_TOTAL * D2];        // pair partials: S_hi*256+S_lo

static __device__ __forceinline__ uint32_t smem_u32(const void* p) {
    uint32_t a;
    asm("{ .reg .u64 t; cvta.to.shared.u64 t, %1; cvt.u32.u64 %0, t; }" : "=r"(a) : "l"(p));
    return a;
}
static __device__ __forceinline__ void cp16(uint32_t s, const void* g) {
    asm volatile("cp.async.cg.shared.global [%0], [%1], 16;" :: "r"(s), "l"(g) : "memory");
}
#define CP_COMMIT()  asm volatile("cp.async.commit_group;" ::: "memory")
#define CP_WAIT2()   asm volatile("cp.async.wait_group 2;" ::: "memory")

static __device__ __forceinline__ void ldsm4(uint32_t* r, uint32_t addr) {
    asm volatile("ldmatrix.sync.aligned.m8n8.x4.shared.b16 {%0,%1,%2,%3}, [%4];"
                 : "=r"(r[0]), "=r"(r[1]), "=r"(r[2]), "=r"(r[3]) : "r"(addr));
}
// s8 mma: D(s32) = A(s8 m16k32 row) * B(s8 k32n8 col) + D — EXACT integer arithmetic
static __device__ __forceinline__ void mma_s8(int* c, const uint32_t* a,
                                              uint32_t b0, uint32_t b1) {
    asm volatile(
        "mma.sync.aligned.m16n8k32.row.col.s32.s8.s8.s32 "
        "{%0,%1,%2,%3}, {%4,%5,%6,%7}, {%8,%9}, {%0,%1,%2,%3};"
        : "+r"(c[0]), "+r"(c[1]), "+r"(c[2]), "+r"(c[3])
        : "r"(a[0]), "r"(a[1]), "r"(a[2]), "r"(a[3]), "r"(b0), "r"(b1));
}
static __device__ __forceinline__ uint32_t swz(int row, int kb) {
    return (uint32_t)(row * 128 + ((kb ^ (row & 7)) << 4));
}
// expand 4 bits -> 4 {0,1} bytes. bit j lands at {j, j+7, j+14, j+21}; extracted
// positions 0/8/16/24 <- j=0/1/2/3 uniquely; |j-j'|<7 => no collisions, NO CARRIES.
static __device__ __forceinline__ uint32_t expand4(uint32_t n) {
    return (n * 0x00204081u) & 0x01010101u;
}

// ---------------- prep kernels ----------------

__global__ void prep_xmask_kernel(const float* __restrict__ x) {
    const size_t nwords = (size_t)M_TOTAL * (D1 / 32);
    const size_t stride = (size_t)gridDim.x * blockDim.x;
    for (size_t gid = (size_t)blockIdx.x * blockDim.x + threadIdx.x; gid < nwords; gid += stride) {
        const float* xp = x + gid * 32;
        float v[32];
#pragma unroll
        for (int i = 0; i < 8; i++) {
            float4 f = *(const float4*)(xp + i * 4);
            v[i * 4 + 0] = f.x; v[i * 4 + 1] = f.y; v[i * 4 + 2] = f.z; v[i * 4 + 3] = f.w;
        }
        uint32_t m = 0;
#pragma unroll
        for (int q = 0; q < 4; q++)
#pragma unroll
            for (int b = 0; b < 4; b++) {
                if (v[4 * q + b]      != 0.0f) m |= 1u << (8 * q + b);
                if (v[16 + 4 * q + b] != 0.0f) m |= 1u << (8 * q + 4 + b);
            }
        g_xmask[gid] = m;
    }
}

__global__ void prep_w_kernel(const float* __restrict__ W) {
    const size_t n = (size_t)D2 * D1;
    const size_t stride = (size_t)gridDim.x * blockDim.x;
    for (size_t i = (size_t)blockIdx.x * blockDim.x + threadIdx.x; i < n; i += stride) {
        double wd = (double)W[i] * 8589934592.0;          // W * 2^33 (exact in double)
        long long I = llrint(wd);
        I = min(max(I, -2130000000LL), 2130000000LL);     // inert safety clamp
        int c3 = (int)((I + 128) & 255) - 128;  I = (I - c3) >> 8;
        int c2 = (int)((I + 128) & 255) - 128;  I = (I - c2) >> 8;
        int c1 = (int)((I + 128) & 255) - 128;  I = (I - c1) >> 8;
        int c0 = (int)I;
        g_w8[i]         = (int8_t)c0;
        g_w8[n + i]     = (int8_t)c1;
        g_w8[2 * n + i] = (int8_t)c2;
        g_w8[3 * n + i] = (int8_t)c3;
    }
}

// ---------------- GEMM: exact fixed-point int8 tensor cores, bitmask A -------------
// grid (32, 256, 2): z = digit-plane pair. 256 threads, 8 warps: 4M x 2N, 32x32 warp tile.
// pair=0: planes c0,c1 -> g_curp[0] = S0*256+S1 (|.| <= 6.7e6 < 2^24, exact fp32)
// pair=1: planes c2,c3 -> g_curp[1] = S2*256+S3

__global__ void __launch_bounds__(256, 2)
gemm_kernel() {
    extern __shared__ char smem[];
    const uint32_t sb = smem_u32(smem);
    const int tid   = threadIdx.x;
    const int wid   = tid >> 5;
    const int lane  = tid & 31;
    const int warpM = wid & 3;           // 0..3 -> 32-row slab
    const int warpN = wid >> 2;          // 0..1 -> 32-col slab
    const int bN    = blockIdx.x;
    const int bM    = blockIdx.y;
    const int pair  = blockIdx.z;

    const size_t wn = (size_t)D2 * D1;
    const int8_t* gB = g_w8 + (size_t)(2 * pair) * wn + (size_t)bN * BN * D1;
    const uint32_t* gM = g_xmask + (size_t)bM * BM * (D1 / 32);  // 64 words/row

    // B ldmatrix per-lane fragment rows / k-halves (validated layout)
    const int b_r  = (lane & 7) + ((lane >> 4) & 1) * 8;
    const int b_ks = (lane >> 3) & 1;
    const uint32_t q4 = 0x4440u | (uint32_t)(lane & 3);   // byte_perm: select byte tq

    int acc[PPL][2][4][4];
#pragma unroll
    for (int p = 0; p < PPL; p++)
#pragma unroll
        for (int mi = 0; mi < 2; mi++)
#pragma unroll
            for (int ni = 0; ni < 4; ni++)
#pragma unroll
                for (int e = 0; e < 4; e++) acc[p][mi][ni][e] = 0;

    // stage loader: B 2*512 cp16 (4/thread) + mask 128 cp16 (tid<128)
    auto load_stage = [&](int kc, int slot) {
        const uint32_t st = sb + slot * STAGE_BYTES;
#pragma unroll
        for (int i = 0; i < 4; i++) {
            const int u  = tid + 256 * i;
            const int sp = u >> 9;                 // local plane 0..1
            const int v  = u & 511;
            const int row = v >> 3, kb = v & 7;    // row 0..63
            cp16(st + sp * B_PLANE + swz(row, kb),
                 gB + (size_t)sp * wn + (size_t)row * D1 + kc * BK + kb * 16);
        }
        if (tid < BM) {
            cp16(st + MASK_OFF + tid * 16, gM + (size_t)tid * (D1 / 32) + kc * 4);
        }
    };

    load_stage(0, 0); CP_COMMIT();
    load_stage(1, 1); CP_COMMIT();
    load_stage(2, 2); CP_COMMIT();

    for (int kc = 0; kc < NCHUNK; kc++) {
        CP_WAIT2();                      // chunk kc resident
        __syncthreads();
        if (kc + 3 < NCHUNK) load_stage(kc + 3, (kc + 3) % NSTAGE);
        CP_COMMIT();                     // empty group near tail keeps wait-count semantics

        const int slot = kc % NSTAGE;
        const uint32_t stB = sb + slot * STAGE_BYTES;
        const char* mbase = smem + slot * STAGE_BYTES + MASK_OFF;

#pragma unroll
        for (int ks = 0; ks < 4; ks++) {             // k32 steps within 128-elem chunk
            // B fragments: one ldsm.x4 per plane per n16 group
            uint32_t bf[PPL][2][4];
#pragma unroll
            for (int p = 0; p < PPL; p++)
#pragma unroll
                for (int ng = 0; ng < 2; ng++)
                    ldsm4(bf[p][ng], stB + p * B_PLANE
                                     + swz(warpN * 32 + ng * 16 + b_r, ks * 2 + b_ks));

            // A fragments from bitmask (exact {0,1} bytes, carry-free nibble expansion)
            uint32_t af[2][4];
#pragma unroll
            for (int mi = 0; mi < 2; mi++) {
                const int row_lo = warpM * 32 + mi * 16 + (lane >> 2);
                const uint32_t mlo = *(const uint32_t*)(mbase + row_lo * 16 + ks * 4);
                const uint32_t mhi = *(const uint32_t*)(mbase + (row_lo + 8) * 16 + ks * 4);
                const uint32_t blo = __byte_perm(mlo, 0, q4);   // byte tq of row g
                const uint32_t bhi = __byte_perm(mhi, 0, q4);   // byte tq of row g+8
                af[mi][0] = expand4(blo & 15u);   // row g,   k-low
                af[mi][2] = expand4(blo >> 4);    // row g,   k-high
                af[mi][1] = expand4(bhi & 15u);   // row g+8, k-low
                af[mi][3] = expand4(bhi >> 4);    // row g+8, k-high
            }

#pragma unroll
            for (int p = 0; p < PPL; p++)
#pragma unroll
                for (int ng = 0; ng < 2; ng++) {
                    mma_s8(acc[p][0][ng * 2 + 0], af[0], bf[p][ng][0], bf[p][ng][1]);
                    mma_s8(acc[p][0][ng * 2 + 1], af[0], bf[p][ng][2], bf[p][ng][3]);
                    mma_s8(acc[p][1][ng * 2 + 0], af[1], bf[p][ng][0], bf[p][ng][1]);
                    mma_s8(acc[p][1][ng * 2 + 1], af[1], bf[p][ng][2], bf[p][ng][3]);
                }
        }
    }

    // epilogue: f = S_hi*256 + S_lo (integer, |.| <= ~6.7e6 < 2^24 -> exact in fp32)
    const int g  = lane >> 2;
    const int tq = lane & 3;
    float* outBase = g_curp[pair] + (size_t)(bM * BM + warpM * 32) * D2 + bN * BN + warpN * 32;
#pragma unroll
    for (int mi = 0; mi < 2; mi++)
#pragma unroll
        for (int ni = 0; ni < 4; ni++) {
            float r[4];
#pragma unroll
            for (int e = 0; e < 4; e++)
                r[e] = (float)(acc[0][mi][ni][e] * 256 + acc[1][mi][ni][e]);
            float* ptr = outBase + (size_t)(mi * 16 + g) * D2 + ni * 8 + tq * 2;
            *(float2*)ptr                    = make_float2(r[0], r[1]);
            *(float2*)(ptr + 8 * (size_t)D2) = make_float2(r[2], r[3]);
        }
}

// ---------------- scan: combine pairs + recurrence over t ----------------
// cur = f01*2^-17 + f23*2^-33; single rounding of the exact fixed-point value.

__global__ void __launch_bounds__(256, 8)
scan_kernel(float* __restrict__ out) {
    const int gid = blockIdx.x * blockDim.x + threadIdx.x;   // 0..131071
    const size_t base = (size_t)gid * 4;

    const float ALPHA = (float)(1.0 - 0.001 / 0.005);  // 0.8
    const float BETA  = (float)(1.0 - 0.001 / 0.01);   // 0.9

    float syn[4] = {0, 0, 0, 0}, mem[4] = {0, 0, 0, 0};
    for (int t = 0; t < T_STEPS; t++) {
        const size_t idx = (size_t)t * BATCH * D2 + base;
        float4 f01 = *(const float4*)(g_curp[0] + idx);
        float4 f23 = *(const float4*)(g_curp[1] + idx);
        const float a01[4] = {f01.x, f01.y, f01.z, f01.w};
        const float a23[4] = {f23.x, f23.y, f23.z, f23.w};
        float4 spk;
        float* sv = (float*)&spk;
#pragma unroll
        for (int e = 0; e < 4; e++) {
            const float cur = fmaf(a01[e], 0x1p-17f, a23[e] * 0x1p-33f);
            syn[e] = ALPHA * syn[e] + cur;
            float mn = BETA * mem[e] + syn[e];
            if (mem[e] > 1.0f) mn = 0.0f;            // zero reset (uses previous mem)
            sv[e] = (mn > 1.0f) ? 1.0f : 0.0f;
            mem[e] = mn;
        }
        *(float4*)(out + idx) = spk;
    }
}

extern "C" void kernel_launch(void* const* d_in, const int* in_sizes, int n_in,
                              void* d_out, int out_size) {
    const float* x = (const float*)d_in[0];   // [T, B, D1]
    const float* W = (const float*)d_in[1];   // [D2, D1]
    float* out = (float*)d_out;               // [T, B, D2]

    cudaFuncSetAttribute(gemm_kernel, cudaFuncAttributeMaxDynamicSharedMemorySize, SMEM_BYTES);

    prep_xmask_kernel<<<4096, 256>>>(x);
    prep_w_kernel<<<4096, 256>>>(W);

    dim3 grid(D2 / BN, M_TOTAL / BM, 2);      // (32, 256, 2) -- both pairs in one launch
    gemm_kernel<<<grid, 256, SMEM_BYTES>>>();

    scan_kernel<<<(BATCH * D2 / 4) / 256, 256>>>(out);
}

// round 15
// speedup vs baseline: 1.0711x; 1.0711x over previous
#include <cuda_runtime.h>
#include <cstdint>

#define T_STEPS 128
#define BATCH   256
#define D1      2048
#define D2      2048
#define M_TOTAL (T_STEPS * BATCH)      // 32768 GEMM rows

#define BM 128          // CTA tile M
#define BN 64           // CTA tile N
#define BK 128          // K chunk (int8 elems = one 128B smem row)
#define NSTAGE 3
#define NCHUNK (D1 / BK)               // 16
#define NPLANE 4                       // total digit planes
#define PPL    2                       // planes per launch

#define A_STAGE (BM * 128)                      // 16384
#define B_PLANE (BN * 128)                      // 8192 per digit plane
#define STAGE_BYTES (A_STAGE + PPL * B_PLANE)   // 32768
#define SMEM_BYTES  (NSTAGE * STAGE_BYTES)      // 98304 -> 2 CTAs/SM

__device__ int8_t g_x8[(size_t)M_TOTAL * D1];            // binary x as int8 (exact)
__device__ int8_t g_w8[(size_t)NPLANE * D2 * D1];        // digit planes c0..c3 (W*2^33, base 256)
__device__ float  g_f23[(size_t)M_TOTAL * D2];           // pair-1 partial: S2*256+S3 (exact fp32)
__device__ float  g_cur[(size_t)M_TOTAL * D2];           // final fp32 currents

static __device__ __forceinline__ uint32_t smem_u32(const void* p) {
    uint32_t a;
    asm("{ .reg .u64 t; cvta.to.shared.u64 t, %1; cvt.u32.u64 %0, t; }" : "=r"(a) : "l"(p));
    return a;
}
static __device__ __forceinline__ void cp16(uint32_t s, const void* g) {
    asm volatile("cp.async.cg.shared.global [%0], [%1], 16;" :: "r"(s), "l"(g) : "memory");
}
#define CP_COMMIT()  asm volatile("cp.async.commit_group;" ::: "memory")
#define CP_WAIT1()   asm volatile("cp.async.wait_group 1;" ::: "memory")

static __device__ __forceinline__ void ldsm4(uint32_t* r, uint32_t addr) {
    asm volatile("ldmatrix.sync.aligned.m8n8.x4.shared.b16 {%0,%1,%2,%3}, [%4];"
                 : "=r"(r[0]), "=r"(r[1]), "=r"(r[2]), "=r"(r[3]) : "r"(addr));
}
// s8 mma: D(s32) = A(s8 m16k32 row) * B(s8 k32n8 col) + D — EXACT integer arithmetic
static __device__ __forceinline__ void mma_s8(int* c, const uint32_t* a,
                                              uint32_t b0, uint32_t b1) {
    asm volatile(
        "mma.sync.aligned.m16n8k32.row.col.s32.s8.s8.s32 "
        "{%0,%1,%2,%3}, {%4,%5,%6,%7}, {%8,%9}, {%0,%1,%2,%3};"
        : "+r"(c[0]), "+r"(c[1]), "+r"(c[2]), "+r"(c[3])
        : "r"(a[0]), "r"(a[1]), "r"(a[2]), "r"(a[3]), "r"(b0), "r"(b1));
}
static __device__ __forceinline__ uint32_t swz(int row, int kb) {
    return (uint32_t)(row * 128 + ((kb ^ (row & 7)) << 4));
}

// ---------------- prep kernels ----------------

__global__ void prep_x_kernel(const float* __restrict__ x) {
    const size_t n = (size_t)M_TOTAL * D1;
    const size_t stride = (size_t)gridDim.x * blockDim.x * 4;
    for (size_t i = ((size_t)blockIdx.x * blockDim.x + threadIdx.x) * 4; i < n; i += stride) {
        float4 v = *(const float4*)(x + i);
        char4 c;
        c.x = (char)v.x; c.y = (char)v.y; c.z = (char)v.z; c.w = (char)v.w;  // x in {0.0, 1.0}
        *(char4*)(g_x8 + i) = c;
    }
}

__global__ void prep_w_kernel(const float* __restrict__ W) {
    const size_t n = (size_t)D2 * D1;
    const size_t stride = (size_t)gridDim.x * blockDim.x;
    for (size_t i = (size_t)blockIdx.x * blockDim.x + threadIdx.x; i < n; i += stride) {
        // W * 2^33 is EXACT in fp32 (pow-2 multiply = exponent shift), so
        // llrintf of it equals llrint of the exact real product. No fp64 needed.
        float z = W[i] * 8589934592.0f;                   // W * 2^33, exact
        long long I = llrintf(z);
        I = min(max(I, -2130000000LL), 2130000000LL);     // inert safety clamp (|W|<0.25)
        int c3 = (int)((I + 128) & 255) - 128;  I = (I - c3) >> 8;
        int c2 = (int)((I + 128) & 255) - 128;  I = (I - c2) >> 8;
        int c1 = (int)((I + 128) & 255) - 128;  I = (I - c1) >> 8;
        int c0 = (int)I;
        g_w8[i]         = (int8_t)c0;
        g_w8[n + i]     = (int8_t)c1;
        g_w8[2 * n + i] = (int8_t)c2;
        g_w8[3 * n + i] = (int8_t)c3;
    }
}

// ---------------- GEMM: exact fixed-point via int8 tensor cores, 2 planes/launch ----
// grid (32, 256), 256 threads, 8 warps: 4M x 2N grid -> warp tile 32(M) x 32(N)
// Launch order: pair=1 FIRST (writes raw f23 = S2*256+S3 to g_f23), then pair=0
// (computes f01 = S0*256+S1, reads f23, writes final cur = f01*2^-17 + f23*2^-33).
// Both partials are integers |.| <= ~6.7e6 < 2^24 -> exact in fp32; the fmaf single-
// rounds the exact fixed-point total => bit-identical to R11/R13 (rel_err 0.0).

__global__ void __launch_bounds__(256, 2)
gemm_kernel(int pair) {
    extern __shared__ char smem[];
    const uint32_t sb = smem_u32(smem);
    const int tid   = threadIdx.x;
    const int wid   = tid >> 5;
    const int lane  = tid & 31;
    const int warpM = wid & 3;           // 0..3 -> 32-row slab
    const int warpN = wid >> 2;          // 0..1 -> 32-col slab
    const int bN    = blockIdx.x;
    const int bM    = blockIdx.y;

    const size_t wn = (size_t)D2 * D1;
    const int8_t* gA = g_x8 + (size_t)bM * BM * D1;
    const int8_t* gB = g_w8 + (size_t)(2 * pair) * wn + (size_t)bN * BN * D1;

    // ldmatrix per-lane fragment rows and 16B-chunk parities (validated layout)
    const int a_r  = (lane & 7) + ((lane >> 3) & 1) * 8;
    const int a_ks = lane >> 4;
    const int b_r  = (lane & 7) + ((lane >> 4) & 1) * 8;
    const int b_ks = (lane >> 3) & 1;

    int acc[PPL][2][4][4];
#pragma unroll
    for (int p = 0; p < PPL; p++)
#pragma unroll
        for (int mi = 0; mi < 2; mi++)
#pragma unroll
            for (int ni = 0; ni < 4; ni++)
#pragma unroll
                for (int e = 0; e < 4; e++) acc[p][mi][ni][e] = 0;

    // stage loader: A 1024 + B 2*512 16B chunks, 8 per thread
    auto load_stage = [&](int kc, int slot) {
        const uint32_t st = sb + slot * STAGE_BYTES;
#pragma unroll
        for (int i = 0; i < 4; i++) {
            const int u = tid + 256 * i;
            const int row = u >> 3, kb = u & 7;
            cp16(st + swz(row, kb), gA + (size_t)row * D1 + kc * BK + kb * 16);
        }
#pragma unroll
        for (int i = 0; i < 4; i++) {
            const int u  = tid + 256 * i;
            const int sp = u >> 9;                 // local plane 0..1
            const int v  = u & 511;
            const int row = v >> 3, kb = v & 7;    // row 0..63
            cp16(st + A_STAGE + sp * B_PLANE + swz(row, kb),
                 gB + (size_t)sp * wn + (size_t)row * D1 + kc * BK + kb * 16);
        }
    };

    load_stage(0, 0); CP_COMMIT();
    load_stage(1, 1); CP_COMMIT();

    for (int kc = 0; kc < NCHUNK; kc++) {
        CP_WAIT1();
        __syncthreads();
        if (kc + 2 < NCHUNK) load_stage(kc + 2, (kc + 2) % NSTAGE);
        CP_COMMIT();

        const uint32_t stA = sb + (kc % NSTAGE) * STAGE_BYTES;
        const uint32_t stB = stA + A_STAGE;
#pragma unroll
        for (int ks = 0; ks < 4; ks++) {             // k32 steps within 128-elem chunk
            uint32_t af[2][4];
            uint32_t bf[PPL][2][4];
#pragma unroll
            for (int mi = 0; mi < 2; mi++)
                ldsm4(af[mi], stA + swz(warpM * 32 + mi * 16 + a_r, ks * 2 + a_ks));
#pragma unroll
            for (int p = 0; p < PPL; p++)
#pragma unroll
                for (int ng = 0; ng < 2; ng++)
                    ldsm4(bf[p][ng], stB + p * B_PLANE
                                     + swz(warpN * 32 + ng * 16 + b_r, ks * 2 + b_ks));
#pragma unroll
            for (int p = 0; p < PPL; p++)
#pragma unroll
                for (int ng = 0; ng < 2; ng++) {
                    mma_s8(acc[p][0][ng * 2 + 0], af[0], bf[p][ng][0], bf[p][ng][1]);
                    mma_s8(acc[p][0][ng * 2 + 1], af[0], bf[p][ng][2], bf[p][ng][3]);
                    mma_s8(acc[p][1][ng * 2 + 0], af[1], bf[p][ng][0], bf[p][ng][1]);
                    mma_s8(acc[p][1][ng * 2 + 1], af[1], bf[p][ng][2], bf[p][ng][3]);
                }
        }
    }

    // epilogue
    const int g  = lane >> 2;
    const int tq = lane & 3;
    const size_t tileOff = (size_t)(bM * BM + warpM * 32) * D2 + bN * BN + warpN * 32;
    if (pair == 1) {
        // raw partial f23 = S2*256 + S3 (exact fp32)
        float* outBase = g_f23 + tileOff;
#pragma unroll
        for (int mi = 0; mi < 2; mi++)
#pragma unroll
            for (int ni = 0; ni < 4; ni++) {
                float r[4];
#pragma unroll
                for (int e = 0; e < 4; e++)
                    r[e] = (float)(acc[0][mi][ni][e] * 256 + acc[1][mi][ni][e]);
                float* ptr = outBase + (size_t)(mi * 16 + g) * D2 + ni * 8 + tq * 2;
                *(float2*)ptr                    = make_float2(r[0], r[1]);
                *(float2*)(ptr + 8 * (size_t)D2) = make_float2(r[2], r[3]);
            }
    } else {
        // combine: cur = f01*2^-17 + f23*2^-33 (single rounding of exact fixed point)
        const float* inBase = g_f23 + tileOff;
        float* outBase = g_cur + tileOff;
#pragma unroll
        for (int mi = 0; mi < 2; mi++)
#pragma unroll
            for (int ni = 0; ni < 4; ni++) {
                const size_t o0 = (size_t)(mi * 16 + g) * D2 + ni * 8 + tq * 2;
                const size_t o1 = o0 + 8 * (size_t)D2;
                float2 f23a = *(const float2*)(inBase + o0);
                float2 f23b = *(const float2*)(inBase + o1);
                float f01_0 = (float)(acc[0][mi][ni][0] * 256 + acc[1][mi][ni][0]);
                float f01_1 = (float)(acc[0][mi][ni][1] * 256 + acc[1][mi][ni][1]);
                float f01_2 = (float)(acc[0][mi][ni][2] * 256 + acc[1][mi][ni][2]);
                float f01_3 = (float)(acc[0][mi][ni][3] * 256 + acc[1][mi][ni][3]);
                *(float2*)(outBase + o0) = make_float2(
                    fmaf(f01_0, 0x1p-17f, f23a.x * 0x1p-33f),
                    fmaf(f01_1, 0x1p-17f, f23a.y * 0x1p-33f));
                *(float2*)(outBase + o1) = make_float2(
                    fmaf(f01_2, 0x1p-17f, f23b.x * 0x1p-33f),
                    fmaf(f01_3, 0x1p-17f, f23b.y * 0x1p-33f));
            }
    }
}

// ---------------- scan: recurrence over t, elementwise in (b, d2) ----------------

__global__ void __launch_bounds__(256, 8)
scan_kernel(float* __restrict__ out) {
    const int gid = blockIdx.x * blockDim.x + threadIdx.x;   // 0..131071
    const size_t base = (size_t)gid * 4;

    const float ALPHA = (float)(1.0 - 0.001 / 0.005);  // 0.8
    const float BETA  = (float)(1.0 - 0.001 / 0.01);   // 0.9

    float syn[4] = {0, 0, 0, 0}, mem[4] = {0, 0, 0, 0};
    for (int t = 0; t < T_STEPS; t++) {
        const size_t idx = (size_t)t * BATCH * D2 + base;
        float4 cur = *(const float4*)(g_cur + idx);
        const float cv[4] = {cur.x, cur.y, cur.z, cur.w};
        float4 spk;
        float* sv = (float*)&spk;
#pragma unroll
        for (int e = 0; e < 4; e++) {
            syn[e] = ALPHA * syn[e] + cv[e];
            float mn = BETA * mem[e] + syn[e];
            if (mem[e] > 1.0f) mn = 0.0f;            // zero reset (uses previous mem)
            sv[e] = (mn > 1.0f) ? 1.0f : 0.0f;
            mem[e] = mn;
        }
        *(float4*)(out + idx) = spk;
    }
}

extern "C" void kernel_launch(void* const* d_in, const int* in_sizes, int n_in,
                              void* d_out, int out_size) {
    const float* x = (const float*)d_in[0];   // [T, B, D1]
    const float* W = (const float*)d_in[1];   // [D2, D1]
    float* out = (float*)d_out;               // [T, B, D2]

    cudaFuncSetAttribute(gemm_kernel, cudaFuncAttributeMaxDynamicSharedMemorySize, SMEM_BYTES);

    prep_x_kernel<<<4096, 256>>>(x);
    prep_w_kernel<<<4096, 256>>>(W);

    dim3 grid(D2 / BN, M_TOTAL / BM);         // (32, 256)
    gemm_kernel<<<grid, 256, SMEM_BYTES>>>(1);   // planes c2,c3 -> raw f23
    gemm_kernel<<<grid, 256, SMEM_BYTES>>>(0);   // planes c0,c1 -> combined final cur

    scan_kernel<<<(BATCH * D2 / 4) / 256, 256>>>(out);
}

// round 16
// speedup vs baseline: 1.1013x; 1.0282x over previous
#include <cuda_runtime.h>
#include <cstdint>

#define T_STEPS 128
#define BATCH   256
#define D1      2048
#define D2      2048
#define M_TOTAL (T_STEPS * BATCH)      // 32768 GEMM rows

#define BM 128          // CTA tile M
#define BN 64           // CTA tile N
#define BK 128          // K chunk (int8 elems = one 128B smem row)
#define NSTAGE 3
#define NCHUNK (D1 / BK)               // 16
#define NPLANE 4                       // total digit planes
#define PPL    2                       // planes per pair

#define A_STAGE (BM * 128)                      // 16384
#define B_PLANE (BN * 128)                      // 8192 per digit plane
#define STAGE_BYTES (A_STAGE + PPL * B_PLANE)   // 32768
#define SMEM_BYTES  (NSTAGE * STAGE_BYTES)      // 98304 -> 2 CTAs/SM

__device__ int8_t g_x8[(size_t)M_TOTAL * D1];            // binary x as int8 (exact)
__device__ int8_t g_w8[(size_t)NPLANE * D2 * D1];        // digit planes c0..c3 (W*2^33, base 256)
__device__ float  g_curp[2][(size_t)M_TOTAL * D2];       // pair partials: S_hi*256+S_lo (exact fp32)

static __device__ __forceinline__ uint32_t smem_u32(const void* p) {
    uint32_t a;
    asm("{ .reg .u64 t; cvta.to.shared.u64 t, %1; cvt.u32.u64 %0, t; }" : "=r"(a) : "l"(p));
    return a;
}
static __device__ __forceinline__ void cp16(uint32_t s, const void* g) {
    asm volatile("cp.async.cg.shared.global [%0], [%1], 16;" :: "r"(s), "l"(g) : "memory");
}
#define CP_COMMIT()  asm volatile("cp.async.commit_group;" ::: "memory")
#define CP_WAIT1()   asm volatile("cp.async.wait_group 1;" ::: "memory")

static __device__ __forceinline__ void ldsm4(uint32_t* r, uint32_t addr) {
    asm volatile("ldmatrix.sync.aligned.m8n8.x4.shared.b16 {%0,%1,%2,%3}, [%4];"
                 : "=r"(r[0]), "=r"(r[1]), "=r"(r[2]), "=r"(r[3]) : "r"(addr));
}
// s8 mma: D(s32) = A(s8 m16k32 row) * B(s8 k32n8 col) + D — EXACT integer arithmetic
static __device__ __forceinline__ void mma_s8(int* c, const uint32_t* a,
                                              uint32_t b0, uint32_t b1) {
    asm volatile(
        "mma.sync.aligned.m16n8k32.row.col.s32.s8.s8.s32 "
        "{%0,%1,%2,%3}, {%4,%5,%6,%7}, {%8,%9}, {%0,%1,%2,%3};"
        : "+r"(c[0]), "+r"(c[1]), "+r"(c[2]), "+r"(c[3])
        : "r"(a[0]), "r"(a[1]), "r"(a[2]), "r"(a[3]), "r"(b0), "r"(b1));
}
static __device__ __forceinline__ uint32_t swz(int row, int kb) {
    return (uint32_t)(row * 128 + ((kb ^ (row & 7)) << 4));
}

// ---------------- prep kernels ----------------

__global__ void prep_x_kernel(const float* __restrict__ x) {
    const size_t n = (size_t)M_TOTAL * D1;
    const size_t stride = (size_t)gridDim.x * blockDim.x * 4;
    for (size_t i = ((size_t)blockIdx.x * blockDim.x + threadIdx.x) * 4; i < n; i += stride) {
        float4 v = *(const float4*)(x + i);
        char4 c;
        c.x = (char)v.x; c.y = (char)v.y; c.z = (char)v.z; c.w = (char)v.w;  // x in {0.0, 1.0}
        *(char4*)(g_x8 + i) = c;
    }
}

__global__ void prep_w_kernel(const float* __restrict__ W) {
    const size_t n = (size_t)D2 * D1;
    const size_t stride = (size_t)gridDim.x * blockDim.x;
    for (size_t i = (size_t)blockIdx.x * blockDim.x + threadIdx.x; i < n; i += stride) {
        // W * 2^33 is EXACT in fp32 (pow-2 multiply = exponent shift), so
        // llrintf of it equals llrint of the exact real product. No fp64 needed.
        float z = W[i] * 8589934592.0f;                   // W * 2^33, exact
        long long I = llrintf(z);
        I = min(max(I, -2130000000LL), 2130000000LL);     // inert safety clamp (|W|<0.25)
        int c3 = (int)((I + 128) & 255) - 128;  I = (I - c3) >> 8;
        int c2 = (int)((I + 128) & 255) - 128;  I = (I - c2) >> 8;
        int c1 = (int)((I + 128) & 255) - 128;  I = (I - c1) >> 8;
        int c0 = (int)I;
        g_w8[i]         = (int8_t)c0;
        g_w8[n + i]     = (int8_t)c1;
        g_w8[2 * n + i] = (int8_t)c2;
        g_w8[3 * n + i] = (int8_t)c3;
    }
}

// ---------------- GEMM: exact fixed-point via int8 tensor cores, 2 planes/pair -----
// grid (32, 256, 2): z = digit-plane pair (z-major order == two sequential launches).
// 256 threads, 8 warps: 4M x 2N grid -> warp tile 32(M) x 32(N).
// pair=0: planes c0,c1 -> g_curp[0] = S0*256+S1 (|.| <= 6.7e6 < 2^24, exact fp32)
// pair=1: planes c2,c3 -> g_curp[1] = S2*256+S3

__global__ void __launch_bounds__(256, 2)
gemm_kernel() {
    extern __shared__ char smem[];
    const uint32_t sb = smem_u32(smem);
    const int tid   = threadIdx.x;
    const int wid   = tid >> 5;
    const int lane  = tid & 31;
    const int warpM = wid & 3;           // 0..3 -> 32-row slab
    const int warpN = wid >> 2;          // 0..1 -> 32-col slab
    const int bN    = blockIdx.x;
    const int bM    = blockIdx.y;
    const int pair  = blockIdx.z;

    const size_t wn = (size_t)D2 * D1;
    const int8_t* gA = g_x8 + (size_t)bM * BM * D1;
    const int8_t* gB = g_w8 + (size_t)(2 * pair) * wn + (size_t)bN * BN * D1;

    // ldmatrix per-lane fragment rows and 16B-chunk parities (validated layout)
    const int a_r  = (lane & 7) + ((lane >> 3) & 1) * 8;
    const int a_ks = lane >> 4;
    const int b_r  = (lane & 7) + ((lane >> 4) & 1) * 8;
    const int b_ks = (lane >> 3) & 1;

    int acc[PPL][2][4][4];
#pragma unroll
    for (int p = 0; p < PPL; p++)
#pragma unroll
        for (int mi = 0; mi < 2; mi++)
#pragma unroll
            for (int ni = 0; ni < 4; ni++)
#pragma unroll
                for (int e = 0; e < 4; e++) acc[p][mi][ni][e] = 0;

    // stage loader: A 1024 + B 2*512 16B chunks, 8 per thread
    auto load_stage = [&](int kc, int slot) {
        const uint32_t st = sb + slot * STAGE_BYTES;
#pragma unroll
        for (int i = 0; i < 4; i++) {
            const int u = tid + 256 * i;
            const int row = u >> 3, kb = u & 7;
            cp16(st + swz(row, kb), gA + (size_t)row * D1 + kc * BK + kb * 16);
        }
#pragma unroll
        for (int i = 0; i < 4; i++) {
            const int u  = tid + 256 * i;
            const int sp = u >> 9;                 // local plane 0..1
            const int v  = u & 511;
            const int row = v >> 3, kb = v & 7;    // row 0..63
            cp16(st + A_STAGE + sp * B_PLANE + swz(row, kb),
                 gB + (size_t)sp * wn + (size_t)row * D1 + kc * BK + kb * 16);
        }
    };

    load_stage(0, 0); CP_COMMIT();
    load_stage(1, 1); CP_COMMIT();

    for (int kc = 0; kc < NCHUNK; kc++) {
        CP_WAIT1();
        __syncthreads();
        if (kc + 2 < NCHUNK) load_stage(kc + 2, (kc + 2) % NSTAGE);
        CP_COMMIT();

        const uint32_t stA = sb + (kc % NSTAGE) * STAGE_BYTES;
        const uint32_t stB = stA + A_STAGE;
#pragma unroll
        for (int ks = 0; ks < 4; ks++) {             // k32 steps within 128-elem chunk
            uint32_t af[2][4];
            uint32_t bf[PPL][2][4];
#pragma unroll
            for (int mi = 0; mi < 2; mi++)
                ldsm4(af[mi], stA + swz(warpM * 32 + mi * 16 + a_r, ks * 2 + a_ks));
#pragma unroll
            for (int p = 0; p < PPL; p++)
#pragma unroll
                for (int ng = 0; ng < 2; ng++)
                    ldsm4(bf[p][ng], stB + p * B_PLANE
                                     + swz(warpN * 32 + ng * 16 + b_r, ks * 2 + b_ks));
#pragma unroll
            for (int p = 0; p < PPL; p++)
#pragma unroll
                for (int ng = 0; ng < 2; ng++) {
                    mma_s8(acc[p][0][ng * 2 + 0], af[0], bf[p][ng][0], bf[p][ng][1]);
                    mma_s8(acc[p][0][ng * 2 + 1], af[0], bf[p][ng][2], bf[p][ng][3]);
                    mma_s8(acc[p][1][ng * 2 + 0], af[1], bf[p][ng][0], bf[p][ng][1]);
                    mma_s8(acc[p][1][ng * 2 + 1], af[1], bf[p][ng][2], bf[p][ng][3]);
                }
        }
    }

    // epilogue: f = S_hi*256 + S_lo (integer, |.| <= ~6.7e6 < 2^24 -> exact in fp32)
    const int g  = lane >> 2;
    const int tq = lane & 3;
    float* outBase = g_curp[pair] + (size_t)(bM * BM + warpM * 32) * D2 + bN * BN + warpN * 32;
#pragma unroll
    for (int mi = 0; mi < 2; mi++)
#pragma unroll
        for (int ni = 0; ni < 4; ni++) {
            float r[4];
#pragma unroll
            for (int e = 0; e < 4; e++)
                r[e] = (float)(acc[0][mi][ni][e] * 256 + acc[1][mi][ni][e]);
            float* ptr = outBase + (size_t)(mi * 16 + g) * D2 + ni * 8 + tq * 2;
            *(float2*)ptr                    = make_float2(r[0], r[1]);
            *(float2*)(ptr + 8 * (size_t)D2) = make_float2(r[2], r[3]);
        }
}

// ---------------- scan: combine pairs + recurrence over t ----------------
// cur = f01*2^-17 + f23*2^-33; f23*2^-33 exact (pow2), fma -> single rounding of the
// exact fixed-point value => bit-identical to the single-convert version (rel_err 0.0).

__global__ void __launch_bounds__(256, 8)
scan_kernel(float* __restrict__ out) {
    const int gid = blockIdx.x * blockDim.x + threadIdx.x;   // 0..131071
    const size_t base = (size_t)gid * 4;

    const float ALPHA = (float)(1.0 - 0.001 / 0.005);  // 0.8
    const float BETA  = (float)(1.0 - 0.001 / 0.01);   // 0.9

    float syn[4] = {0, 0, 0, 0}, mem[4] = {0, 0, 0, 0};
    for (int t = 0; t < T_STEPS; t++) {
        const size_t idx = (size_t)t * BATCH * D2 + base;
        float4 f01 = *(const float4*)(g_curp[0] + idx);
        float4 f23 = *(const float4*)(g_curp[1] + idx);
        const float a01[4] = {f01.x, f01.y, f01.z, f01.w};
        const float a23[4] = {f23.x, f23.y, f23.z, f23.w};
        float4 spk;
        float* sv = (float*)&spk;
#pragma unroll
        for (int e = 0; e < 4; e++) {
            const float cur = fmaf(a01[e], 0x1p-17f, a23[e] * 0x1p-33f);
            syn[e] = ALPHA * syn[e] + cur;
            float mn = BETA * mem[e] + syn[e];
            if (mem[e] > 1.0f) mn = 0.0f;            // zero reset (uses previous mem)
            sv[e] = (mn > 1.0f) ? 1.0f : 0.0f;
            mem[e] = mn;
        }
        *(float4*)(out + idx) = spk;
    }
}

extern "C" void kernel_launch(void* const* d_in, const int* in_sizes, int n_in,
                              void* d_out, int out_size) {
    const float* x = (const float*)d_in[0];   // [T, B, D1]
    const float* W = (const float*)d_in[1];   // [D2, D1]
    float* out = (float*)d_out;               // [T, B, D2]

    cudaFuncSetAttribute(gemm_kernel, cudaFuncAttributeMaxDynamicSharedMemorySize, SMEM_BYTES);

    prep_x_kernel<<<4096, 256>>>(x);
    prep_w_kernel<<<4096, 256>>>(W);

    dim3 grid(D2 / BN, M_TOTAL / BM, 2);      // (32, 256, 2): both pairs, one launch
    gemm_kernel<<<grid, 256, SMEM_BYTES>>>();

    scan_kernel<<<(BATCH * D2 / 4) / 256, 256>>>(out);
}